// round 10
// baseline (speedup 1.0000x reference)
#include <cuda_runtime.h>
#include <cstdint>

// ---------------------------------------------------------------------------
// BiLSTM-CRF: gather -> input GEMM -> cluster-resident LSTM (fwd+bwd as two
// 8-CTA clusters, register W_hh, DSMEM st.async h-exchange + mbarrier; the
// R6 configuration that measured fastest) -> linear -> CRF forward
// (exp-factorized with exact underflow fallback) + Viterbi.
// ---------------------------------------------------------------------------

#define SEQ   4096
#define EMB   500
#define HID   200
#define G4    800      // 4*HID
#define NT    50
#define TSTART 48
#define TEND   49
#define NEGV  (-10000.0f)
#define NBLK  8        // CTAs per direction (= cluster size)
#define JS    25       // HID / NBLK
#define ROWS  100      // 4*JS gate rows per CTA

// ------------------------------ scratch -----------------------------------
__device__ float g_x[SEQ * EMB];
__device__ float g_xproj[2][SEQ * G4];
__device__ float g_hseq[2][SEQ * HID];
__device__ float g_feats[SEQ * NT];

// --------------------------- PTX helpers -----------------------------------
__device__ __forceinline__ uint32_t smem_u32(const void* p) {
    uint32_t a;
    asm("{ .reg .u64 t; cvta.to.shared.u64 t, %1; cvt.u32.u64 %0, t; }"
        : "=r"(a) : "l"(p));
    return a;
}
__device__ __forceinline__ uint32_t mapa32(uint32_t a, uint32_t rank) {
    uint32_t d;
    asm("mapa.shared::cluster.u32 %0, %1, %2;" : "=r"(d) : "r"(a), "r"(rank));
    return d;
}
__device__ __forceinline__ void mbar_init(uint32_t a, uint32_t n) {
    asm volatile("mbarrier.init.shared.b64 [%0], %1;" :: "r"(a), "r"(n) : "memory");
}
__device__ __forceinline__ void mbar_arrive_expect_tx(uint32_t a, uint32_t tx) {
    asm volatile("mbarrier.arrive.expect_tx.shared.b64 _, [%0], %1;"
                 :: "r"(a), "r"(tx) : "memory");
}
__device__ __forceinline__ void mbar_wait_cluster_acq(uint32_t a, uint32_t ph) {
    asm volatile(
        "{\n\t.reg .pred P;\n"
        "LW_%=:\n\t"
        "mbarrier.try_wait.parity.acquire.cluster.shared::cta.b64 P, [%0], %1, 0x989680;\n\t"
        "@P bra LD_%=;\n\t"
        "bra LW_%=;\n"
        "LD_%=:\n\t}"
        :: "r"(a), "r"(ph) : "memory");
}
__device__ __forceinline__ void st_async_u32(uint32_t raddr, uint32_t v, uint32_t rmbar) {
    asm volatile("st.async.shared::cluster.mbarrier::complete_tx::bytes.u32 [%0], %1, [%2];"
                 :: "r"(raddr), "r"(v), "r"(rmbar) : "memory");
}
__device__ __forceinline__ void cluster_sync_all() {
    asm volatile("barrier.cluster.arrive.aligned;" ::: "memory");
    asm volatile("barrier.cluster.wait.aligned;" ::: "memory");
}

__device__ __forceinline__ float sigfast(float x) {
    return __fdividef(1.f, 1.f + __expf(-x));
}
__device__ __forceinline__ float tanhfast(float x) {
    return 1.f - 2.f * __fdividef(1.f, __expf(2.f * x) + 1.f);
}

// ------------------------------ gather ------------------------------------
__global__ void k_gather(const int* __restrict__ ids, const float* __restrict__ emb) {
    int idx = blockIdx.x * blockDim.x + threadIdx.x;   // SEQ * 125 float4
    if (idx < SEQ * 125) {
        int t = idx / 125, c = idx % 125;
        const float4* src = reinterpret_cast<const float4*>(emb + (size_t)ids[t] * EMB);
        reinterpret_cast<float4*>(g_x)[t * 125 + c] = src[c];
    }
}

// --------------------------- input projection GEMM ------------------------
__global__ void k_xproj(const float* __restrict__ wf, const float* __restrict__ wb,
                        const float* __restrict__ bihf, const float* __restrict__ bhhf,
                        const float* __restrict__ bihb, const float* __restrict__ bhhb) {
    const int dir = blockIdx.z;
    const float* __restrict__ W = dir ? wb : wf;
    __shared__ float As[16][68];
    __shared__ float Bs[16][68];
    const int m0 = blockIdx.y * 64, n0 = blockIdx.x * 64;
    const int tid = threadIdx.x;
    const int tx = tid & 15, ty = tid >> 4;
    float acc[4][4] = {};
    for (int k0 = 0; k0 < EMB; k0 += 16) {
        #pragma unroll
        for (int e = 0; e < 4; e++) {
            int L = tid + 256 * e;
            int r = L >> 4, kk = L & 15;
            bool kok = (k0 + kk) < EMB;
            int gm = m0 + r;
            int srcRow = dir ? (SEQ - 1 - gm) : gm;
            As[kk][r] = kok ? g_x[(size_t)srcRow * EMB + k0 + kk] : 0.f;
            int gn = n0 + r;
            Bs[kk][r] = (kok && gn < G4) ? W[(size_t)gn * EMB + k0 + kk] : 0.f;
        }
        __syncthreads();
        #pragma unroll
        for (int kk = 0; kk < 16; kk++) {
            float a[4], b[4];
            #pragma unroll
            for (int i = 0; i < 4; i++) a[i] = As[kk][ty * 4 + i];
            #pragma unroll
            for (int j = 0; j < 4; j++) b[j] = Bs[kk][tx * 4 + j];
            #pragma unroll
            for (int i = 0; i < 4; i++)
                #pragma unroll
                for (int j = 0; j < 4; j++) acc[i][j] += a[i] * b[j];
        }
        __syncthreads();
    }
    #pragma unroll
    for (int i = 0; i < 4; i++) {
        int gm = m0 + ty * 4 + i;
        #pragma unroll
        for (int j = 0; j < 4; j++) {
            int gn = n0 + tx * 4 + j;
            if (gn < G4) {
                float bias = dir ? (bihb[gn] + bhhb[gn]) : (bihf[gn] + bhhf[gn]);
                g_xproj[dir][(size_t)gm * G4 + gn] = acc[i][j] + bias;
            }
        }
    }
}

// ------------------------------ LSTM ---------------------------------------
// R6 configuration (measured fastest): 2 clusters of 8 CTAs, 256 threads.
// Each CTA owns 25 h elements (100 gate rows), W_hh rows in registers,
// scalar float4 dot with pair-in-warp k-split via psh, per-step exchange of
// the 200-float h via 200 st.async.u32 + transaction mbarrier (all threads
// wait).
__global__ void __launch_bounds__(256, 1) __cluster_dims__(NBLK, 1, 1)
k_lstm(const float* __restrict__ whf, const float* __restrict__ whb,
       const float* __restrict__ h0, const float* __restrict__ c0) {
    const int dir = blockIdx.x >> 3;
    uint32_t rank;
    asm("mov.u32 %0, %%cluster_ctarank;" : "=r"(rank));
    const int j0 = (int)rank * JS;
    const float* __restrict__ Whh = dir ? whb : whf;
    const int tid = threadIdx.x;
    const int wid = tid >> 5, lane = tid & 31;
    const int khalf = wid >> 2;                 // 0: k[0..99], 1: k[100..199]
    const int row = (wid & 3) * 32 + lane;      // 0..127, active < 100
    const bool act = row < ROWS;

    __shared__ __align__(16) float hbuf[2][HID];
    __shared__ float psh[128];
    __shared__ float gsh[ROWS];
    __shared__ float hloc[JS];
    __shared__ __align__(8) uint64_t mbar[2];

    // weights: rows gate*HID + j0 + jj, half k-slice each
    int gr = 0;
    float w[100];
    if (act) {
        int gate = row / JS, jj = row % JS;
        gr = gate * HID + j0 + jj;
        const float4* wr4 = reinterpret_cast<const float4*>(
            Whh + (size_t)gr * HID + khalf * 100);
        #pragma unroll
        for (int i = 0; i < 25; i++) {
            float4 v = wr4[i];
            w[4 * i + 0] = v.x; w[4 * i + 1] = v.y;
            w[4 * i + 2] = v.z; w[4 * i + 3] = v.w;
        }
    } else {
        #pragma unroll
        for (int i = 0; i < 100; i++) w[i] = 0.f;
    }

    float cst = 0.f;
    if (tid < JS) cst = c0[dir * HID + j0 + tid];
    if (tid < HID) hbuf[0][tid] = h0[dir * HID + tid];

    const uint32_t mb0 = smem_u32(&mbar[0]);
    const uint32_t mb1 = smem_u32(&mbar[1]);
    if (tid == 0) {
        mbar_init(mb0, 1);
        mbar_init(mb1, 1);
        mbar_arrive_expect_tx(mb0, HID * 4);   // will receive h^1
        mbar_arrive_expect_tx(mb1, HID * 4);   // will receive h^0
    }

    // precompute remote slots for both parities (tid < 200 are senders)
    const int sr = tid / JS;                   // target rank
    const int sj = tid % JS;                   // element within our slice
    uint32_t ra0 = 0, ra1 = 0, rb0 = 0, rb1 = 0;
    if (tid < NBLK * JS) {
        ra0 = mapa32(smem_u32(&hbuf[0][j0 + sj]), (uint32_t)sr);
        ra1 = mapa32(smem_u32(&hbuf[1][j0 + sj]), (uint32_t)sr);
        rb0 = mapa32(mb0, (uint32_t)sr);
        rb1 = mapa32(mb1, (uint32_t)sr);
    }

    // All mbarrier inits + hbuf[0] fills visible cluster-wide before any
    // st.async arrives.
    __syncthreads();
    cluster_sync_all();

    const float* __restrict__ xp_base = &g_xproj[dir][0];

    for (int s = 0; s < SEQ; s++) {
        const int pin = s & 1, pout = pin ^ 1;
        const uint32_t mb_in = pin ? mb1 : mb0;

        // prefetch xp (independent of h) before the barrier wait
        float xp = 0.f;
        if (act && khalf == 0) xp = __ldg(&xp_base[(size_t)s * G4 + gr]);

        if (s > 0) {
            mbar_wait_cluster_acq(mb_in, (uint32_t)(((s - 1) >> 1) & 1));
            if (tid == 0) mbar_arrive_expect_tx(mb_in, HID * 4);  // re-arm for h^{s+1}
        }

        // dot: broadcast LDS.128 of h half, 4 accumulators
        const float4* h4 = reinterpret_cast<const float4*>(&hbuf[pin][khalf * 100]);
        float a0 = 0.f, a1 = 0.f, a2 = 0.f, a3 = 0.f;
        #pragma unroll
        for (int i = 0; i < 25; i++) {
            float4 hv = h4[i];
            a0 += w[4 * i + 0] * hv.x;
            a1 += w[4 * i + 1] * hv.y;
            a2 += w[4 * i + 2] * hv.z;
            a3 += w[4 * i + 3] * hv.w;
        }
        float acc = (a0 + a1) + (a2 + a3);
        if (khalf == 1) psh[row] = acc;
        __syncthreads();
        if (khalf == 0 && act) gsh[row] = acc + psh[row] + xp;
        __syncthreads();

        if (tid < JS) {
            float gi = gsh[tid], gf = gsh[JS + tid];
            float gg = gsh[2 * JS + tid], go = gsh[3 * JS + tid];
            float c = sigfast(gf) * cst + sigfast(gi) * tanhfast(gg);
            float h = sigfast(go) * tanhfast(c);
            cst = c;
            hloc[tid] = h;
            g_hseq[dir][(size_t)s * HID + j0 + tid] = h;
        }
        __syncthreads();

        if (tid < NBLK * JS && s < SEQ - 1) {
            float hv = hloc[sj];
            st_async_u32(pout ? ra1 : ra0, __float_as_uint(hv), pout ? rb1 : rb0);
        }
    }
    // No CTA exits while peers may still reference its SMEM.
    cluster_sync_all();
}

// ------------------------------ linear -------------------------------------
__global__ void k_linear(const float* __restrict__ lw, const float* __restrict__ lb) {
    int t = blockIdx.x;
    __shared__ __align__(16) float hsm[2 * HID];
    int tid = threadIdx.x;                   // 64
    for (int i = tid; i < HID; i += 64) {
        hsm[i] = g_hseq[0][(size_t)t * HID + i];
        hsm[HID + i] = g_hseq[1][(size_t)(SEQ - 1 - t) * HID + i];
    }
    __syncthreads();
    if (tid < NT) {
        const float4* wr = reinterpret_cast<const float4*>(lw + (size_t)tid * 2 * HID);
        const float4* hv = reinterpret_cast<const float4*>(hsm);
        float acc = 0.f;
        #pragma unroll 5
        for (int i = 0; i < 100; i++) {
            float4 wv = wr[i]; float4 h4 = hv[i];
            acc += wv.x * h4.x + wv.y * h4.y + wv.z * h4.z + wv.w * h4.w;
        }
        g_feats[t * NT + tid] = acc + lb[tid];
    }
}

// ------------------------------ CRF ----------------------------------------
// block 0: gold + factorized forward logZ (exact fallback on underflow) +
// loss. Block 0 reuses the dynamic-smem backpointer region for exp(T).
// block 1: viterbi + backtrack (backpointers in dynamic smem).
__global__ void __launch_bounds__(512, 1) k_crf(const float* __restrict__ trans,
                                                const int* __restrict__ tags,
                                                float* __restrict__ out, int out_size) {
    extern __shared__ unsigned char bpS[];   // blk1: SEQ*NT bp; blk0: expT
    __shared__ float trT[64][56];            // trT[j][i] = trans[i][j], raw
    __shared__ float alpha[2][64];
    __shared__ float easm[64];
    __shared__ float wred[16];
    __shared__ float goldsh;
    __shared__ float Msh;
    const int tid = threadIdx.x;

    for (int L = tid; L < 64 * 56; L += 512) (&trT[0][0])[L] = 0.f;
    __syncthreads();
    for (int L = tid; L < NT * NT; L += 512) {
        int i = L / NT, j = L % NT;
        trT[j][i] = trans[L];
    }
    if (tid < 64) {
        alpha[0][tid] = (tid == TSTART) ? 0.f : NEGV;
        alpha[1][tid] = NEGV;                // pads stay NEGV forever
    }
    __syncthreads();

    const int jg = tid >> 3, sub = tid & 7;

    if (blockIdx.x == 0) {
        float* expT = reinterpret_cast<float*>(bpS);   // [64][56], blk0 only

        // ---- gold score ----
        float part = 0.f;
        for (int t = tid; t < SEQ; t += 512) {
            int prev = (t == 0) ? TSTART : tags[t - 1];
            int cur = tags[t];
            part += trans[prev * NT + cur] + g_feats[t * NT + cur];
        }
        #pragma unroll
        for (int d = 16; d > 0; d >>= 1) part += __shfl_xor_sync(0xffffffffu, part, d);
        if ((tid & 31) == 0) wred[tid >> 5] = part;

        // expT[j][i] = exp(T[i][j]); pads = 0
        for (int L = tid; L < 64 * 56; L += 512) expT[L] = 0.f;
        __syncthreads();
        for (int L = tid; L < 64 * 56; L += 512) {
            int j = L / 56, i = L % 56;
            if (j < NT && i < NT) expT[L] = __expf(trT[j][i]);
        }
        if (tid == 0) {
            float g = 0.f;
            for (int i2 = 0; i2 < 16; i2++) g += wred[i2];
            g += trans[tags[SEQ - 1] * NT + TEND];
            goldsh = g;
        }
        __syncthreads();

        // ---- factorized forward scan with exact-underflow fallback:
        //   alpha'_j = M + f_j + log( sum_i exp(alpha_i - M) * exp(T_ij) )
        int p = 0;
        for (int s = 0; s < SEQ; s++) {
            if (tid < 32) {
                float a = fmaxf(alpha[p][tid], alpha[p][tid + 32]);
                #pragma unroll
                for (int d = 16; d > 0; d >>= 1)
                    a = fmaxf(a, __shfl_xor_sync(0xffffffffu, a, d));
                if (tid == 0) Msh = a;
            }
            __syncthreads();
            if (tid < 64)
                easm[tid] = (tid < NT) ? __expf(alpha[p][tid] - Msh) : 0.f;
            __syncthreads();

            float sm = 0.f;
            #pragma unroll
            for (int q = 0; q < 7; q++) {
                int ii = sub + 8 * q;     // <= 55
                sm += easm[ii] * expT[jg * 56 + ii];
            }
            #pragma unroll
            for (int d = 1; d < 8; d <<= 1) sm += __shfl_xor_sync(0xffffffffu, sm, d);
            if (sub == 0 && jg < NT) {
                float fj = g_feats[s * NT + jg];
                float res;
                if (sm > 0.f) {
                    res = Msh + fj + __logf(sm);
                } else {
                    // exact path (rare): direct logsumexp_i(alpha_i + T_ij)
                    float m2 = -3.4e38f;
                    for (int i2 = 0; i2 < NT; i2++)
                        m2 = fmaxf(m2, alpha[p][i2] + trT[jg][i2]);
                    float s2 = 0.f;
                    for (int i2 = 0; i2 < NT; i2++)
                        s2 += __expf(alpha[p][i2] + trT[jg][i2] - m2);
                    res = m2 + __logf(s2) + fj;
                }
                alpha[p ^ 1][jg] = res;
            }
            __syncthreads();
            p ^= 1;
        }
        if (tid == 0) {
            float m = -3.4e38f;
            for (int i2 = 0; i2 < NT; i2++)
                m = fmaxf(m, alpha[p][i2] + trans[i2 * NT + TEND]);
            float sm = 0.f;
            for (int i2 = 0; i2 < NT; i2++)
                sm += __expf((alpha[p][i2] + trans[i2 * NT + TEND]) - m);
            float logZ = m + __logf(sm);
            if (out_size > SEQ) out[SEQ] = logZ - goldsh;
        }
    } else {
        // ---- viterbi scan ----
        int p = 0;
        for (int s = 0; s < SEQ; s++) {
            float fj = (jg < NT) ? g_feats[s * NT + jg] : 0.f;
            float m = -3.4e38f;
            int mi = NT;
            #pragma unroll
            for (int q = 0; q < 7; q++) {
                int ii = sub + 8 * q;
                if (ii < NT) {
                    float v = (alpha[p][ii] + fj) + trT[jg][ii];
                    if (v > m) { m = v; mi = ii; }
                }
            }
            #pragma unroll
            for (int d = 1; d < 8; d <<= 1) {
                float om = __shfl_xor_sync(0xffffffffu, m, d);
                int omi = __shfl_xor_sync(0xffffffffu, mi, d);
                if (om > m || (om == m && omi < mi)) { m = om; mi = omi; }
            }
            if (sub == 0 && jg < NT) {
                alpha[p ^ 1][jg] = m;
                bpS[s * NT + jg] = (unsigned char)mi;
            }
            __syncthreads();
            p ^= 1;
        }
        if (tid == 0) {
            float bm = -3.4e38f;
            int best = 0;
            for (int i2 = 0; i2 < NT; i2++) {
                float v = alpha[p][i2] + trans[i2 * NT + TEND];
                if (v > bm) { bm = v; best = i2; }
            }
            int tag = best;
            out[SEQ - 1] = (float)tag;
            for (int t = SEQ - 2; t >= 0; t--) {
                tag = bpS[(t + 1) * NT + tag];
                out[t] = (float)tag;
            }
        }
    }
}

// ------------------------------ launch -------------------------------------
extern "C" void kernel_launch(void* const* d_in, const int* in_sizes, int n_in,
                              void* d_out, int out_size) {
    const int*   ids   = (const int*)d_in[0];
    const int*   tags  = (const int*)d_in[1];
    const float* emb   = (const float*)d_in[2];
    const float* wihf  = (const float*)d_in[3];
    const float* whhf  = (const float*)d_in[4];
    const float* bihf  = (const float*)d_in[5];
    const float* bhhf  = (const float*)d_in[6];
    const float* wihb  = (const float*)d_in[7];
    const float* whhb  = (const float*)d_in[8];
    const float* bihb  = (const float*)d_in[9];
    const float* bhhb  = (const float*)d_in[10];
    const float* lw    = (const float*)d_in[11];
    const float* lb    = (const float*)d_in[12];
    const float* trans = (const float*)d_in[13];
    const float* h0    = (const float*)d_in[14];
    const float* c0    = (const float*)d_in[15];
    float* out = (float*)d_out;

    (void)in_sizes; (void)n_in;

    cudaFuncSetAttribute(k_crf, cudaFuncAttributeMaxDynamicSharedMemorySize, SEQ * NT);

    k_gather<<<(SEQ * 125 + 255) / 256, 256>>>(ids, emb);
    k_xproj<<<dim3((G4 + 63) / 64, SEQ / 64, 2), 256>>>(wihf, wihb, bihf, bhhf, bihb, bhhb);
    k_lstm<<<2 * NBLK, 256>>>(whhf, whhb, h0, c0);
    k_linear<<<SEQ, 64>>>(lw, lb);
    k_crf<<<2, 512, SEQ * NT>>>(trans, tags, out, out_size);
}

// round 11
// speedup vs baseline: 1.4584x; 1.4584x over previous
#include <cuda_runtime.h>
#include <cstdint>

// ---------------------------------------------------------------------------
// BiLSTM-CRF: fused gather+input GEMM -> cluster-resident LSTM (fwd+bwd as
// two 8-CTA clusters, register W_hh, DSMEM st.async h-exchange + mbarrier;
// R6 protocol, cell threads send directly) -> linear -> CRF (R6 version).
// ---------------------------------------------------------------------------

#define SEQ   4096
#define EMB   500
#define HID   200
#define G4    800      // 4*HID
#define NT    50
#define TSTART 48
#define TEND   49
#define NEGV  (-10000.0f)
#define NBLK  8        // CTAs per direction (= cluster size)
#define JS    25       // HID / NBLK
#define ROWS  100      // 4*JS gate rows per CTA

// ------------------------------ scratch -----------------------------------
__device__ float g_xproj[2][SEQ * G4];
__device__ float g_hseq[2][SEQ * HID];
__device__ float g_feats[SEQ * NT];

// --------------------------- PTX helpers -----------------------------------
__device__ __forceinline__ uint32_t smem_u32(const void* p) {
    uint32_t a;
    asm("{ .reg .u64 t; cvta.to.shared.u64 t, %1; cvt.u32.u64 %0, t; }"
        : "=r"(a) : "l"(p));
    return a;
}
__device__ __forceinline__ uint32_t mapa32(uint32_t a, uint32_t rank) {
    uint32_t d;
    asm("mapa.shared::cluster.u32 %0, %1, %2;" : "=r"(d) : "r"(a), "r"(rank));
    return d;
}
__device__ __forceinline__ void mbar_init(uint32_t a, uint32_t n) {
    asm volatile("mbarrier.init.shared.b64 [%0], %1;" :: "r"(a), "r"(n) : "memory");
}
__device__ __forceinline__ void mbar_arrive_expect_tx(uint32_t a, uint32_t tx) {
    asm volatile("mbarrier.arrive.expect_tx.shared.b64 _, [%0], %1;"
                 :: "r"(a), "r"(tx) : "memory");
}
__device__ __forceinline__ void mbar_wait_cluster_acq(uint32_t a, uint32_t ph) {
    asm volatile(
        "{\n\t.reg .pred P;\n"
        "LW_%=:\n\t"
        "mbarrier.try_wait.parity.acquire.cluster.shared::cta.b64 P, [%0], %1, 0x989680;\n\t"
        "@P bra LD_%=;\n\t"
        "bra LW_%=;\n"
        "LD_%=:\n\t}"
        :: "r"(a), "r"(ph) : "memory");
}
__device__ __forceinline__ void st_async_u32(uint32_t raddr, uint32_t v, uint32_t rmbar) {
    asm volatile("st.async.shared::cluster.mbarrier::complete_tx::bytes.u32 [%0], %1, [%2];"
                 :: "r"(raddr), "r"(v), "r"(rmbar) : "memory");
}
__device__ __forceinline__ void cluster_sync_all() {
    asm volatile("barrier.cluster.arrive.aligned;" ::: "memory");
    asm volatile("barrier.cluster.wait.aligned;" ::: "memory");
}

__device__ __forceinline__ float sigfast(float x) {
    return __fdividef(1.f, 1.f + __expf(-x));
}
__device__ __forceinline__ float tanhfast(float x) {
    return 1.f - 2.f * __fdividef(1.f, __expf(2.f * x) + 1.f);
}

// --------------------- fused gather + input projection ---------------------
__global__ void k_xproj(const int* __restrict__ ids, const float* __restrict__ emb,
                        const float* __restrict__ wf, const float* __restrict__ wb,
                        const float* __restrict__ bihf, const float* __restrict__ bhhf,
                        const float* __restrict__ bihb, const float* __restrict__ bhhb) {
    const int dir = blockIdx.z;
    const float* __restrict__ W = dir ? wb : wf;
    __shared__ float As[16][68];
    __shared__ float Bs[16][68];
    const int m0 = blockIdx.y * 64, n0 = blockIdx.x * 64;
    const int tid = threadIdx.x;
    const int tx = tid & 15, ty = tid >> 4;
    float acc[4][4] = {};
    for (int k0 = 0; k0 < EMB; k0 += 16) {
        #pragma unroll
        for (int e = 0; e < 4; e++) {
            int L = tid + 256 * e;
            int r = L >> 4, kk = L & 15;
            bool kok = (k0 + kk) < EMB;
            int gm = m0 + r;
            int srcRow = dir ? (SEQ - 1 - gm) : gm;
            As[kk][r] = kok ? emb[(size_t)ids[srcRow] * EMB + k0 + kk] : 0.f;
            int gn = n0 + r;
            Bs[kk][r] = (kok && gn < G4) ? W[(size_t)gn * EMB + k0 + kk] : 0.f;
        }
        __syncthreads();
        #pragma unroll
        for (int kk = 0; kk < 16; kk++) {
            float a[4], b[4];
            #pragma unroll
            for (int i = 0; i < 4; i++) a[i] = As[kk][ty * 4 + i];
            #pragma unroll
            for (int j = 0; j < 4; j++) b[j] = Bs[kk][tx * 4 + j];
            #pragma unroll
            for (int i = 0; i < 4; i++)
                #pragma unroll
                for (int j = 0; j < 4; j++) acc[i][j] += a[i] * b[j];
        }
        __syncthreads();
    }
    #pragma unroll
    for (int i = 0; i < 4; i++) {
        int gm = m0 + ty * 4 + i;
        #pragma unroll
        for (int j = 0; j < 4; j++) {
            int gn = n0 + tx * 4 + j;
            if (gn < G4) {
                float bias = dir ? (bihb[gn] + bhhb[gn]) : (bihf[gn] + bhhf[gn]);
                g_xproj[dir][(size_t)gm * G4 + gn] = acc[i][j] + bias;
            }
        }
    }
}

// ------------------------------ LSTM ---------------------------------------
// R6 protocol: 2 clusters of 8 CTAs, 256 threads, W_hh rows in registers,
// scalar float4 dot with k-split via psh, 200 st.async.u32 per step +
// transaction mbarrier (all threads wait). Changes vs R6: cell threads send
// their h directly (no hloc, no 3rd syncthreads) and xp is prefetched one
// step ahead.
__global__ void __launch_bounds__(256, 1) __cluster_dims__(NBLK, 1, 1)
k_lstm(const float* __restrict__ whf, const float* __restrict__ whb,
       const float* __restrict__ h0, const float* __restrict__ c0) {
    const int dir = blockIdx.x >> 3;
    uint32_t rank;
    asm("mov.u32 %0, %%cluster_ctarank;" : "=r"(rank));
    const int j0 = (int)rank * JS;
    const float* __restrict__ Whh = dir ? whb : whf;
    const int tid = threadIdx.x;
    const int wid = tid >> 5, lane = tid & 31;
    const int khalf = wid >> 2;                 // 0: k[0..99], 1: k[100..199]
    const int row = (wid & 3) * 32 + lane;      // 0..127, active < 100
    const bool act = row < ROWS;

    __shared__ __align__(16) float hbuf[2][HID];
    __shared__ float psh[128];
    __shared__ float gsh[ROWS];
    __shared__ __align__(8) uint64_t mbar[2];

    // weights: rows gate*HID + j0 + jj, half k-slice each
    int gr = 0;
    float w[100];
    if (act) {
        int gate = row / JS, jj = row % JS;
        gr = gate * HID + j0 + jj;
        const float4* wr4 = reinterpret_cast<const float4*>(
            Whh + (size_t)gr * HID + khalf * 100);
        #pragma unroll
        for (int i = 0; i < 25; i++) {
            float4 v = wr4[i];
            w[4 * i + 0] = v.x; w[4 * i + 1] = v.y;
            w[4 * i + 2] = v.z; w[4 * i + 3] = v.w;
        }
    } else {
        #pragma unroll
        for (int i = 0; i < 100; i++) w[i] = 0.f;
    }

    float cst = 0.f;
    if (tid < JS) cst = c0[dir * HID + j0 + tid];
    if (tid < HID) hbuf[0][tid] = h0[dir * HID + tid];

    const uint32_t mb0 = smem_u32(&mbar[0]);
    const uint32_t mb1 = smem_u32(&mbar[1]);
    if (tid == 0) {
        mbar_init(mb0, 1);
        mbar_init(mb1, 1);
        mbar_arrive_expect_tx(mb0, HID * 4);   // will receive h^1
        mbar_arrive_expect_tx(mb1, HID * 4);   // will receive h^0
    }

    // cell thread j sends h[j0+j] to all 8 ranks; local slot addresses
    uint32_t la0 = 0, la1 = 0;
    if (tid < JS) {
        la0 = smem_u32(&hbuf[0][j0 + tid]);
        la1 = smem_u32(&hbuf[1][j0 + tid]);
    }

    // mbarrier inits + hbuf[0] visible cluster-wide before any st.async
    __syncthreads();
    cluster_sync_all();

    const float* __restrict__ xp_base = &g_xproj[dir][0];

    // one-step-ahead xp prefetch
    float xp = 0.f, xpn = 0.f;
    if (act && khalf == 0) xp = __ldg(&xp_base[gr]);

    for (int s = 0; s < SEQ; s++) {
        const int pin = s & 1, pout = pin ^ 1;
        const uint32_t mb_in = pin ? mb1 : mb0;

        // prefetch next step's xp (independent of h) before the wait
        if (act && khalf == 0 && s + 1 < SEQ)
            xpn = __ldg(&xp_base[(size_t)(s + 1) * G4 + gr]);

        if (s > 0) {
            mbar_wait_cluster_acq(mb_in, (uint32_t)(((s - 1) >> 1) & 1));
            if (tid == 0) mbar_arrive_expect_tx(mb_in, HID * 4);  // re-arm for s+2
        }

        // dot: broadcast LDS.128 of h half, 4 accumulators
        const float4* h4 = reinterpret_cast<const float4*>(&hbuf[pin][khalf * 100]);
        float a0 = 0.f, a1 = 0.f, a2 = 0.f, a3 = 0.f;
        #pragma unroll
        for (int i = 0; i < 25; i++) {
            float4 hv = h4[i];
            a0 += w[4 * i + 0] * hv.x;
            a1 += w[4 * i + 1] * hv.y;
            a2 += w[4 * i + 2] * hv.z;
            a3 += w[4 * i + 3] * hv.w;
        }
        float acc = (a0 + a1) + (a2 + a3);
        if (khalf == 1) psh[row] = acc;
        __syncthreads();
        if (khalf == 0 && act) gsh[row] = acc + psh[row] + xp;
        __syncthreads();

        if (tid < JS) {
            float gi = gsh[tid], gf = gsh[JS + tid];
            float gg = gsh[2 * JS + tid], go = gsh[3 * JS + tid];
            float c = sigfast(gf) * cst + sigfast(gi) * tanhfast(gg);
            float h = sigfast(go) * tanhfast(c);
            cst = c;
            g_hseq[dir][(size_t)s * HID + j0 + tid] = h;
            if (s < SEQ - 1) {
                // send h to every rank's hbuf[pout][j0+tid] + its mbarrier
                uint32_t hv = __float_as_uint(h);
                uint32_t la = pout ? la1 : la0;
                uint32_t lb = pout ? mb1 : mb0;
                #pragma unroll
                for (int r = 0; r < NBLK; r++)
                    st_async_u32(mapa32(la, (uint32_t)r), hv,
                                 mapa32(lb, (uint32_t)r));
            }
        }
        xp = xpn;
    }
    // No CTA exits while peers may still reference its SMEM.
    cluster_sync_all();
}

// ------------------------------ linear -------------------------------------
__global__ void k_linear(const float* __restrict__ lw, const float* __restrict__ lb) {
    int t = blockIdx.x;
    __shared__ __align__(16) float hsm[2 * HID];
    int tid = threadIdx.x;                   // 64
    for (int i = tid; i < HID; i += 64) {
        hsm[i] = g_hseq[0][(size_t)t * HID + i];
        hsm[HID + i] = g_hseq[1][(size_t)(SEQ - 1 - t) * HID + i];
    }
    __syncthreads();
    if (tid < NT) {
        const float4* wr = reinterpret_cast<const float4*>(lw + (size_t)tid * 2 * HID);
        const float4* hv = reinterpret_cast<const float4*>(hsm);
        float acc = 0.f;
        #pragma unroll 5
        for (int i = 0; i < 100; i++) {
            float4 wv = wr[i]; float4 h4 = hv[i];
            acc += wv.x * h4.x + wv.y * h4.y + wv.z * h4.z + wv.w * h4.w;
        }
        g_feats[t * NT + tid] = acc + lb[tid];
    }
}

// ------------------------------ CRF (R6 version) ----------------------------
// block 0: gold score + forward logZ + loss; block 1: viterbi + backtrack.
__global__ void __launch_bounds__(512, 1) k_crf(const float* __restrict__ trans,
                                                const int* __restrict__ tags,
                                                float* __restrict__ out, int out_size) {
    extern __shared__ unsigned char bpS[];   // SEQ*NT backpointers (block 1)
    __shared__ float trT[64][56];            // trT[j][i] = trans[i][j]
    __shared__ float alpha[2][64];
    __shared__ float wred[16];
    __shared__ float goldsh;
    const int tid = threadIdx.x;

    for (int L = tid; L < 64 * 56; L += 512) (&trT[0][0])[L] = 0.f;
    __syncthreads();
    for (int L = tid; L < NT * NT; L += 512) {
        int i = L / NT, j = L % NT;
        trT[j][i] = trans[L];
    }
    if (tid < 64) alpha[0][tid] = (tid == TSTART) ? 0.f : NEGV;
    __syncthreads();

    const int jg = tid >> 3, sub = tid & 7;

    if (blockIdx.x == 0) {
        float part = 0.f;
        for (int t = tid; t < SEQ; t += 512) {
            int prev = (t == 0) ? TSTART : tags[t - 1];
            int cur = tags[t];
            part += trans[prev * NT + cur] + g_feats[t * NT + cur];
        }
        #pragma unroll
        for (int d = 16; d > 0; d >>= 1) part += __shfl_xor_sync(0xffffffffu, part, d);
        if ((tid & 31) == 0) wred[tid >> 5] = part;
        __syncthreads();
        if (tid == 0) {
            float g = 0.f;
            for (int i2 = 0; i2 < 16; i2++) g += wred[i2];
            g += trans[tags[SEQ - 1] * NT + TEND];
            goldsh = g;
        }
        __syncthreads();

        int p = 0;
        for (int s = 0; s < SEQ; s++) {
            float fj = (jg < NT) ? g_feats[s * NT + jg] : 0.f;
            float vv[7];
            float m = -3.4e38f;
            #pragma unroll
            for (int q = 0; q < 7; q++) {
                int ii = sub + 8 * q;
                float v = (ii < NT) ? (alpha[p][ii] + trT[jg][ii]) + fj : -3.4e38f;
                vv[q] = v;
                m = fmaxf(m, v);
            }
            #pragma unroll
            for (int d = 1; d < 8; d <<= 1) m = fmaxf(m, __shfl_xor_sync(0xffffffffu, m, d));
            float sm = 0.f;
            #pragma unroll
            for (int q = 0; q < 7; q++) sm += __expf(vv[q] - m);
            #pragma unroll
            for (int d = 1; d < 8; d <<= 1) sm += __shfl_xor_sync(0xffffffffu, sm, d);
            if (sub == 0 && jg < NT) alpha[p ^ 1][jg] = m + __logf(sm);
            __syncthreads();
            p ^= 1;
        }
        if (tid == 0) {
            float m = -3.4e38f;
            for (int i2 = 0; i2 < NT; i2++)
                m = fmaxf(m, alpha[p][i2] + trans[i2 * NT + TEND]);
            float sm = 0.f;
            for (int i2 = 0; i2 < NT; i2++)
                sm += __expf((alpha[p][i2] + trans[i2 * NT + TEND]) - m);
            float logZ = m + __logf(sm);
            if (out_size > SEQ) out[SEQ] = logZ - goldsh;
        }
    } else {
        int p = 0;
        for (int s = 0; s < SEQ; s++) {
            float fj = (jg < NT) ? g_feats[s * NT + jg] : 0.f;
            float m = -3.4e38f;
            int mi = NT;
            #pragma unroll
            for (int q = 0; q < 7; q++) {
                int ii = sub + 8 * q;
                if (ii < NT) {
                    float v = (alpha[p][ii] + fj) + trT[jg][ii];
                    if (v > m) { m = v; mi = ii; }
                }
            }
            #pragma unroll
            for (int d = 1; d < 8; d <<= 1) {
                float om = __shfl_xor_sync(0xffffffffu, m, d);
                int omi = __shfl_xor_sync(0xffffffffu, mi, d);
                if (om > m || (om == m && omi < mi)) { m = om; mi = omi; }
            }
            if (sub == 0 && jg < NT) {
                alpha[p ^ 1][jg] = m;
                bpS[s * NT + jg] = (unsigned char)mi;
            }
            __syncthreads();
            p ^= 1;
        }
        if (tid == 0) {
            float bm = -3.4e38f;
            int best = 0;
            for (int i2 = 0; i2 < NT; i2++) {
                float v = alpha[p][i2] + trans[i2 * NT + TEND];
                if (v > bm) { bm = v; best = i2; }
            }
            int tag = best;
            out[SEQ - 1] = (float)tag;
            for (int t = SEQ - 2; t >= 0; t--) {
                tag = bpS[(t + 1) * NT + tag];
                out[t] = (float)tag;
            }
        }
    }
}

// ------------------------------ launch -------------------------------------
extern "C" void kernel_launch(void* const* d_in, const int* in_sizes, int n_in,
                              void* d_out, int out_size) {
    const int*   ids   = (const int*)d_in[0];
    const int*   tags  = (const int*)d_in[1];
    const float* emb   = (const float*)d_in[2];
    const float* wihf  = (const float*)d_in[3];
    const float* whhf  = (const float*)d_in[4];
    const float* bihf  = (const float*)d_in[5];
    const float* bhhf  = (const float*)d_in[6];
    const float* wihb  = (const float*)d_in[7];
    const float* whhb  = (const float*)d_in[8];
    const float* bihb  = (const float*)d_in[9];
    const float* bhhb  = (const float*)d_in[10];
    const float* lw    = (const float*)d_in[11];
    const float* lb    = (const float*)d_in[12];
    const float* trans = (const float*)d_in[13];
    const float* h0    = (const float*)d_in[14];
    const float* c0    = (const float*)d_in[15];
    float* out = (float*)d_out;

    (void)in_sizes; (void)n_in;

    cudaFuncSetAttribute(k_crf, cudaFuncAttributeMaxDynamicSharedMemorySize, SEQ * NT);

    k_xproj<<<dim3((G4 + 63) / 64, SEQ / 64, 2), 256>>>(ids, emb, wihf, wihb,
                                                        bihf, bhhf, bihb, bhhb);
    k_lstm<<<2 * NBLK, 256>>>(whhf, whhb, h0, c0);
    k_linear<<<SEQ, 64>>>(lw, lb);
    k_crf<<<2, 512, SEQ * NT>>>(trans, tags, out, out_size);
}